// round 2
// baseline (speedup 1.0000x reference)
#include <cuda_runtime.h>

#define BB 4
#define TT 32
#define NN 32
#define FF 16
#define GH 64
#define LSTM_IN 2048
#define LSTM_H 4096
#define G4 16384
#define EE 256

// Static scratch (no runtime allocation allowed)
__device__ float d_A[NN * NN];                 // dense normalized adjacency
__device__ float d_seq[BB * TT * LSTM_IN];     // GCN output, 1 MB
__device__ float d_XP[BB * TT * G4];           // x_proj = seq @ W_ih^T + b, 8 MB
__device__ float d_H[2][BB * LSTM_H];          // hidden, ping-pong
__device__ float d_C[BB * LSTM_H];             // cell state

// ---------------------------------------------------------------------------
// Build dense adjacency A[dst][src] with sym-norm + self loops; zero states.
// Detects whether edge_index is int64 or int32 at runtime (JAX x64-disabled
// silently downgrades int64 -> int32).
// ---------------------------------------------------------------------------
__global__ void k_setup(const long long* __restrict__ e64,
                        const int* __restrict__ e32) {
    __shared__ float sdeg[NN];
    __shared__ float sdinv[NN];
    __shared__ float sA[NN * NN];
    __shared__ int s_is64;
    int tid = threadIdx.x;

    if (tid == 0) s_is64 = 1;
    if (tid < NN) sdeg[tid] = 1.0f;  // self loop
    for (int i = tid; i < NN * NN; i += blockDim.x) sA[i] = 0.f;
    __syncthreads();

    // dtype sniff: first 256 int64 words are in-bounds either way
    {
        long long v = e64[tid];  // tid in [0,256)
        if (v < 0 || v >= NN) atomicExch(&s_is64, 0);
    }
    __syncthreads();
    int is64 = s_is64;

    // degree of dst
    {
        int d = is64 ? (int)e64[EE + tid] : e32[EE + tid];
        if (d >= 0 && d < NN) atomicAdd(&sdeg[d], 1.0f);
    }
    __syncthreads();
    if (tid < NN) sdinv[tid] = rsqrtf(sdeg[tid]);
    __syncthreads();
    {
        int s = is64 ? (int)e64[tid]      : e32[tid];
        int d = is64 ? (int)e64[EE + tid] : e32[EE + tid];
        if (s >= 0 && s < NN && d >= 0 && d < NN)
            atomicAdd(&sA[d * NN + s], sdinv[s] * sdinv[d]);
    }
    __syncthreads();
    if (tid < NN) atomicAdd(&sA[tid * NN + tid], sdinv[tid] * sdinv[tid]);
    __syncthreads();
    for (int i = tid; i < NN * NN; i += blockDim.x) d_A[i] = sA[i];
    float* h = &d_H[0][0];
    for (int i = tid; i < 2 * BB * LSTM_H; i += blockDim.x) h[i] = 0.f;
    for (int i = tid; i < BB * LSTM_H; i += blockDim.x) d_C[i] = 0.f;
}

// ---------------------------------------------------------------------------
// Fused LayerNorm + GCN1 + GCN2 per (b,t) slice. 128 blocks x 256 threads.
// ---------------------------------------------------------------------------
__global__ void k_gcn(const float* __restrict__ x,
                      const float* __restrict__ ln_g, const float* __restrict__ ln_b,
                      const float* __restrict__ W1, const float* __restrict__ b1,
                      const float* __restrict__ W2, const float* __restrict__ b2) {
    __shared__ float sA[NN * NN];
    __shared__ float sW1[FF * GH];
    __shared__ float sW2[GH * GH];
    __shared__ float sx[NN][FF];
    __shared__ float sb1[NN][GH];
    __shared__ float sb2[NN][GH];
    int tid = threadIdx.x;
    int bt = blockIdx.x;  // b*32+t
    const float* xb = x + bt * NN * FF;

    for (int i = tid; i < NN * NN; i += 256) sA[i] = d_A[i];
    for (int i = tid; i < FF * GH; i += 256) sW1[i] = W1[i];
    for (int i = tid; i < GH * GH; i += 256) sW2[i] = W2[i];
    if (tid < NN) {
        float mu = 0.f;
        #pragma unroll
        for (int f = 0; f < FF; f++) mu += xb[tid * FF + f];
        mu *= (1.0f / FF);
        float var = 0.f;
        #pragma unroll
        for (int f = 0; f < FF; f++) { float d = xb[tid * FF + f] - mu; var += d * d; }
        var *= (1.0f / FF);
        float rs = rsqrtf(var + 1e-5f);
        #pragma unroll
        for (int f = 0; f < FF; f++)
            sx[tid][f] = (xb[tid * FF + f] - mu) * rs * ln_g[f] + ln_b[f];
    }
    __syncthreads();
    // h1 = ln(x) @ W1
    for (int i = tid; i < NN * GH; i += 256) {
        int n = i >> 6, g = i & 63;
        float s = 0.f;
        #pragma unroll
        for (int f = 0; f < FF; f++) s += sx[n][f] * sW1[f * GH + g];
        sb1[n][g] = s;
    }
    __syncthreads();
    // agg1 = A @ h1 + b1
    for (int i = tid; i < NN * GH; i += 256) {
        int n = i >> 6, g = i & 63;
        float s = b1[g];
        #pragma unroll
        for (int m = 0; m < NN; m++) s += sA[n * NN + m] * sb1[m][g];
        sb2[n][g] = s;
    }
    __syncthreads();
    // h2 = agg1 @ W2
    for (int i = tid; i < NN * GH; i += 256) {
        int n = i >> 6, g = i & 63;
        float s = 0.f;
        #pragma unroll
        for (int k = 0; k < GH; k++) s += sb2[n][k] * sW2[k * GH + g];
        sb1[n][g] = s;
    }
    __syncthreads();
    // agg2 = A @ h2 + b2 -> seq
    for (int i = tid; i < NN * GH; i += 256) {
        int n = i >> 6, g = i & 63;
        float s = b2[g];
        #pragma unroll
        for (int m = 0; m < NN; m++) s += sA[n * NN + m] * sb1[m][g];
        d_seq[bt * LSTM_IN + i] = s;
    }
}

// ---------------------------------------------------------------------------
// x_proj[bt][row] = seq[bt] . W_ih[row] + b_ih[row] + b_hh[row]
// warp = one row x 16 bt columns; grid (2048 row-groups of 8, 8 bt-groups)
// ---------------------------------------------------------------------------
__global__ void k_xproj(const float* __restrict__ Wih,
                        const float* __restrict__ bih,
                        const float* __restrict__ bhh) {
    int lane = threadIdx.x & 31;
    int warp = threadIdx.x >> 5;
    int row = blockIdx.x * 8 + warp;
    int bt0 = blockIdx.y * 16;
    const float4* Wr = (const float4*)(Wih + (size_t)row * LSTM_IN);
    float acc[16];
    #pragma unroll
    for (int j = 0; j < 16; j++) acc[j] = 0.f;
    #pragma unroll 4
    for (int kc = 0; kc < LSTM_IN / 128; kc++) {  // 16 chunks
        float4 w = Wr[kc * 32 + lane];
        #pragma unroll
        for (int j = 0; j < 16; j++) {
            float4 s = ((const float4*)(d_seq + (size_t)(bt0 + j) * LSTM_IN))[kc * 32 + lane];
            acc[j] += w.x * s.x + w.y * s.y + w.z * s.z + w.w * s.w;
        }
    }
    #pragma unroll
    for (int j = 0; j < 16; j++)
        #pragma unroll
        for (int o = 16; o; o >>= 1) acc[j] += __shfl_xor_sync(0xffffffffu, acc[j], o);
    if (lane == 0) {
        float bias = bih[row] + bhh[row];
        #pragma unroll
        for (int j = 0; j < 16; j++)
            d_XP[(size_t)(bt0 + j) * G4 + row] = acc[j] + bias;
    }
}

// ---------------------------------------------------------------------------
// One LSTM step. Warp w owns unit j=w: computes rows j (i), j+4096 (f),
// j+8192 (g), j+12288 (o) for 4 batches, reduces in-warp, updates c/h.
// 512 blocks x 256 threads = 4096 warps. h ping-pong on parity of t.
// ---------------------------------------------------------------------------
__global__ void k_step(const float* __restrict__ Whh, int t) {
    int gw = (blockIdx.x * blockDim.x + threadIdx.x) >> 5;  // unit 0..4095
    int lane = threadIdx.x & 31;
    const float* hin = d_H[t & 1];
    float* hout = d_H[(t + 1) & 1];
    float acc[4][4];
    #pragma unroll
    for (int r = 0; r < 4; r++)
        #pragma unroll
        for (int b = 0; b < 4; b++) acc[r][b] = 0.f;

    const float4* h4 = (const float4*)hin;
    #pragma unroll 4
    for (int kc = 0; kc < LSTM_H / 128; kc++) {  // 32 chunks
        int ki = kc * 32 + lane;
        float4 hv[4];
        #pragma unroll
        for (int b = 0; b < 4; b++) hv[b] = h4[b * (LSTM_H / 4) + ki];
        #pragma unroll
        for (int r = 0; r < 4; r++) {
            float4 w = ((const float4*)(Whh + (size_t)(gw + r * LSTM_H) * LSTM_H))[ki];
            #pragma unroll
            for (int b = 0; b < 4; b++)
                acc[r][b] += w.x * hv[b].x + w.y * hv[b].y + w.z * hv[b].z + w.w * hv[b].w;
        }
    }
    #pragma unroll
    for (int r = 0; r < 4; r++)
        #pragma unroll
        for (int b = 0; b < 4; b++)
            #pragma unroll
            for (int o = 16; o; o >>= 1)
                acc[r][b] += __shfl_xor_sync(0xffffffffu, acc[r][b], o);

    if (lane == 0) {
        #pragma unroll
        for (int b = 0; b < 4; b++) {
            size_t xb = ((size_t)b * TT + t) * G4;
            float gi = acc[0][b] + d_XP[xb + gw];
            float gf = acc[1][b] + d_XP[xb + gw + 4096];
            float gg = acc[2][b] + d_XP[xb + gw + 8192];
            float go = acc[3][b] + d_XP[xb + gw + 12288];
            float si = 1.f / (1.f + expf(-gi));
            float sf = 1.f / (1.f + expf(-gf));
            float so = 1.f / (1.f + expf(-go));
            float c = sf * d_C[b * LSTM_H + gw] + si * tanhf(gg);
            d_C[b * LSTM_H + gw] = c;
            hout[b * LSTM_H + gw] = so * tanhf(c);
        }
    }
}

// ---------------------------------------------------------------------------
// Final FC: out[b][n] = h_last[b][n*128:+128] . fc_W + fc_b
// ---------------------------------------------------------------------------
__global__ void k_fc(const float* __restrict__ fcW, const float* __restrict__ fcb,
                     float* __restrict__ out) {
    int i = threadIdx.x;  // 0..127
    int b = i >> 5, n = i & 31;
    const float* h = &d_H[0][0] + b * LSTM_H + n * 128;  // T=32 steps -> parity 0
    float s = 0.f;
    #pragma unroll
    for (int l = 0; l < 128; l++) s += h[l] * fcW[l];
    out[i] = s + fcb[0];
}

extern "C" void kernel_launch(void* const* d_in, const int* in_sizes, int n_in,
                              void* d_out, int out_size) {
    const float* x       = (const float*)d_in[0];
    const void*  ei      = d_in[1];
    const float* ln_g    = (const float*)d_in[2];
    const float* ln_b    = (const float*)d_in[3];
    const float* W1      = (const float*)d_in[4];
    const float* b1      = (const float*)d_in[5];
    const float* W2      = (const float*)d_in[6];
    const float* b2      = (const float*)d_in[7];
    const float* Wih     = (const float*)d_in[8];
    const float* bih     = (const float*)d_in[9];
    const float* Whh     = (const float*)d_in[10];
    const float* bhh     = (const float*)d_in[11];
    const float* fcW     = (const float*)d_in[12];
    const float* fcb     = (const float*)d_in[13];

    k_setup<<<1, 256>>>((const long long*)ei, (const int*)ei);
    k_gcn<<<BB * TT, 256>>>(x, ln_g, ln_b, W1, b1, W2, b2);
    dim3 gx(G4 / 8, 8);
    k_xproj<<<gx, 256>>>(Wih, bih, bhh);
    for (int t = 0; t < TT; t++) k_step<<<512, 256>>>(Whh, t);
    k_fc<<<1, 128>>>(fcW, fcb, (float*)d_out);
}

// round 3
// speedup vs baseline: 1.3646x; 1.3646x over previous
#include <cuda_runtime.h>
#include <cuda_fp16.h>

#define BB 4
#define TT 32
#define NN 32
#define FF 16
#define GH 64
#define LSTM_IN 2048
#define LSTM_H 4096
#define G4 16384
#define EE 256

typedef unsigned long long u64t;

// Static scratch (no runtime allocation allowed)
__device__ float d_A[NN * NN];
__device__ float d_seq[BB * TT * LSTM_IN];        // GCN output, 1 MB
__device__ float d_XP[BB * TT * G4];              // x_proj, 8 MB
__device__ float d_H[2][BB * LSTM_H];             // hidden ping-pong
__device__ float d_C[BB * LSTM_H];                // cell state
__device__ __half d_Whh[(size_t)G4 * LSTM_H];     // fp16 W_hh, 134 MB
__device__ __half d_Wih[(size_t)G4 * LSTM_IN];    // fp16 W_ih, 67 MB

// ---- f32x2 packed-FMA helpers (full fp32 precision, 2x FFMA rate) ----------
__device__ __forceinline__ void fma2(u64t& d, u64t a, u64t b) {
    asm("fma.rn.f32x2 %0, %1, %2, %0;" : "+l"(d) : "l"(a), "l"(b));
}
__device__ __forceinline__ u64t pkf2(float x, float y) {
    u64t r; asm("mov.b64 %0, {%1, %2};" : "=l"(r) : "f"(x), "f"(y)); return r;
}
__device__ __forceinline__ float2 upk(u64t v) {
    float2 f; asm("mov.b64 {%0, %1}, %2;" : "=f"(f.x), "=f"(f.y) : "l"(v)); return f;
}
// half2 -> packed f32x2
__device__ __forceinline__ u64t h2f2(unsigned h2) {
    u64t r;
    asm("{.reg .f16 lo, hi;\n\t"
        " .reg .f32 flo, fhi;\n\t"
        " mov.b32 {lo, hi}, %1;\n\t"
        " cvt.f32.f16 flo, lo;\n\t"
        " cvt.f32.f16 fhi, hi;\n\t"
        " mov.b64 %0, {flo, fhi};}"
        : "=l"(r) : "r"(h2));
    return r;
}

// ---------------------------------------------------------------------------
// fp32 -> fp16 conversion, 8 elements/thread
// ---------------------------------------------------------------------------
__global__ void k_cvt(const float* __restrict__ src, __half* __restrict__ dst, int n8) {
    int i = blockIdx.x * blockDim.x + threadIdx.x;
    if (i >= n8) return;
    const float4* s4 = (const float4*)src;
    float4 a = s4[(size_t)i * 2], b = s4[(size_t)i * 2 + 1];
    union { __half2 h[4]; uint4 u; } o;
    o.h[0] = __floats2half2_rn(a.x, a.y);
    o.h[1] = __floats2half2_rn(a.z, a.w);
    o.h[2] = __floats2half2_rn(b.x, b.y);
    o.h[3] = __floats2half2_rn(b.z, b.w);
    ((uint4*)dst)[i] = o.u;
}

// ---------------------------------------------------------------------------
// Dense adjacency (sym-norm + self loops); zero h/c. Runtime int32/64 sniff.
// ---------------------------------------------------------------------------
__global__ void k_setup(const long long* __restrict__ e64,
                        const int* __restrict__ e32) {
    __shared__ float sdeg[NN];
    __shared__ float sdinv[NN];
    __shared__ float sA[NN * NN];
    __shared__ int s_is64;
    int tid = threadIdx.x;

    if (tid == 0) s_is64 = 1;
    if (tid < NN) sdeg[tid] = 1.0f;
    for (int i = tid; i < NN * NN; i += blockDim.x) sA[i] = 0.f;
    __syncthreads();
    {
        long long v = e64[tid];
        if (v < 0 || v >= NN) atomicExch(&s_is64, 0);
    }
    __syncthreads();
    int is64 = s_is64;
    {
        int d = is64 ? (int)e64[EE + tid] : e32[EE + tid];
        if (d >= 0 && d < NN) atomicAdd(&sdeg[d], 1.0f);
    }
    __syncthreads();
    if (tid < NN) sdinv[tid] = rsqrtf(sdeg[tid]);
    __syncthreads();
    {
        int s = is64 ? (int)e64[tid]      : e32[tid];
        int d = is64 ? (int)e64[EE + tid] : e32[EE + tid];
        if (s >= 0 && s < NN && d >= 0 && d < NN)
            atomicAdd(&sA[d * NN + s], sdinv[s] * sdinv[d]);
    }
    __syncthreads();
    if (tid < NN) atomicAdd(&sA[tid * NN + tid], sdinv[tid] * sdinv[tid]);
    __syncthreads();
    for (int i = tid; i < NN * NN; i += blockDim.x) d_A[i] = sA[i];
    float* h = &d_H[0][0];
    for (int i = tid; i < 2 * BB * LSTM_H; i += blockDim.x) h[i] = 0.f;
    for (int i = tid; i < BB * LSTM_H; i += blockDim.x) d_C[i] = 0.f;
}

// ---------------------------------------------------------------------------
// Fused LayerNorm + GCN1 + GCN2 per (b,t) slice.
// ---------------------------------------------------------------------------
__global__ void k_gcn(const float* __restrict__ x,
                      const float* __restrict__ ln_g, const float* __restrict__ ln_b,
                      const float* __restrict__ W1, const float* __restrict__ b1,
                      const float* __restrict__ W2, const float* __restrict__ b2) {
    __shared__ float sA[NN * NN];
    __shared__ float sW1[FF * GH];
    __shared__ float sW2[GH * GH];
    __shared__ float sx[NN][FF];
    __shared__ float sb1[NN][GH];
    __shared__ float sb2[NN][GH];
    int tid = threadIdx.x;
    int bt = blockIdx.x;
    const float* xb = x + bt * NN * FF;

    for (int i = tid; i < NN * NN; i += 256) sA[i] = d_A[i];
    for (int i = tid; i < FF * GH; i += 256) sW1[i] = W1[i];
    for (int i = tid; i < GH * GH; i += 256) sW2[i] = W2[i];
    if (tid < NN) {
        float mu = 0.f;
        #pragma unroll
        for (int f = 0; f < FF; f++) mu += xb[tid * FF + f];
        mu *= (1.0f / FF);
        float var = 0.f;
        #pragma unroll
        for (int f = 0; f < FF; f++) { float d = xb[tid * FF + f] - mu; var += d * d; }
        var *= (1.0f / FF);
        float rs = rsqrtf(var + 1e-5f);
        #pragma unroll
        for (int f = 0; f < FF; f++)
            sx[tid][f] = (xb[tid * FF + f] - mu) * rs * ln_g[f] + ln_b[f];
    }
    __syncthreads();
    for (int i = tid; i < NN * GH; i += 256) {
        int n = i >> 6, g = i & 63;
        float s = 0.f;
        #pragma unroll
        for (int f = 0; f < FF; f++) s += sx[n][f] * sW1[f * GH + g];
        sb1[n][g] = s;
    }
    __syncthreads();
    for (int i = tid; i < NN * GH; i += 256) {
        int n = i >> 6, g = i & 63;
        float s = b1[g];
        #pragma unroll
        for (int m = 0; m < NN; m++) s += sA[n * NN + m] * sb1[m][g];
        sb2[n][g] = s;
    }
    __syncthreads();
    for (int i = tid; i < NN * GH; i += 256) {
        int n = i >> 6, g = i & 63;
        float s = 0.f;
        #pragma unroll
        for (int k = 0; k < GH; k++) s += sb2[n][k] * sW2[k * GH + g];
        sb1[n][g] = s;
    }
    __syncthreads();
    for (int i = tid; i < NN * GH; i += 256) {
        int n = i >> 6, g = i & 63;
        float s = b2[g];
        #pragma unroll
        for (int m = 0; m < NN; m++) s += sA[n * NN + m] * sb1[m][g];
        d_seq[bt * LSTM_IN + i] = s;
    }
}

// ---------------------------------------------------------------------------
// x_proj: warp = 2 rows x 16 bt, fp16 W_ih, f32x2 packed FMA, lanes split K.
// grid (1024, 8) x 256 threads.
// ---------------------------------------------------------------------------
__global__ void __launch_bounds__(256) k_xproj(const float* __restrict__ bih,
                                               const float* __restrict__ bhh) {
    int lane = threadIdx.x & 31;
    int w = threadIdx.x >> 5;
    int row = blockIdx.x * 16 + w * 2;   // rows row, row+1
    int bt0 = blockIdx.y * 16;

    u64t acc[2][16];
    #pragma unroll
    for (int r = 0; r < 2; r++)
        #pragma unroll
        for (int j = 0; j < 16; j++) acc[r][j] = 0ull;

    const uint4* W0 = (const uint4*)(d_Wih + (size_t)row * LSTM_IN);
    const uint4* W1 = (const uint4*)(d_Wih + (size_t)(row + 1) * LSTM_IN);

    #pragma unroll 2
    for (int kc = 0; kc < 8; kc++) {
        int g = kc * 32 + lane;          // granule of 8 k
        uint4 wa = W0[g], wb = W1[g];
        u64t wA0 = h2f2(wa.x), wA1 = h2f2(wa.y), wA2 = h2f2(wa.z), wA3 = h2f2(wa.w);
        u64t wB0 = h2f2(wb.x), wB1 = h2f2(wb.y), wB2 = h2f2(wb.z), wB3 = h2f2(wb.w);
        #pragma unroll
        for (int j = 0; j < 16; j++) {
            const float4* S = (const float4*)(d_seq + (size_t)(bt0 + j) * LSTM_IN);
            float4 s0 = S[g * 2], s1 = S[g * 2 + 1];
            u64t p0 = pkf2(s0.x, s0.y), p1 = pkf2(s0.z, s0.w);
            u64t p2 = pkf2(s1.x, s1.y), p3 = pkf2(s1.z, s1.w);
            fma2(acc[0][j], wA0, p0); fma2(acc[0][j], wA1, p1);
            fma2(acc[0][j], wA2, p2); fma2(acc[0][j], wA3, p3);
            fma2(acc[1][j], wB0, p0); fma2(acc[1][j], wB1, p1);
            fma2(acc[1][j], wB2, p2); fma2(acc[1][j], wB3, p3);
        }
    }
    #pragma unroll
    for (int r = 0; r < 2; r++) {
        #pragma unroll
        for (int j = 0; j < 16; j++) {
            float2 f = upk(acc[r][j]);
            float v = f.x + f.y;
            #pragma unroll
            for (int o = 16; o; o >>= 1) v += __shfl_xor_sync(0xffffffffu, v, o);
            if (lane == 0) {
                int rr = row + r;
                d_XP[(size_t)(bt0 + j) * G4 + rr] = v + bih[rr] + bhh[rr];
            }
        }
    }
}

// ---------------------------------------------------------------------------
// One LSTM step, fp16 W_hh. Warp owns unit gw: gate rows gw+{0,1,2,3}*4096,
// 4 batches; in-warp reduce; lane 0 does the nonlinearity + c/h update.
// ---------------------------------------------------------------------------
__global__ void __launch_bounds__(256) k_step(int t) {
    int gw = (blockIdx.x * 256 + threadIdx.x) >> 5;
    int lane = threadIdx.x & 31;
    const float* hin = d_H[t & 1];
    float* hout = d_H[(t + 1) & 1];
    float acc[4][4];
    #pragma unroll
    for (int r = 0; r < 4; r++)
        #pragma unroll
        for (int b = 0; b < 4; b++) acc[r][b] = 0.f;

    const float4* h4 = (const float4*)hin;
    #pragma unroll 4
    for (int kc = 0; kc < 16; kc++) {
        int g = kc * 32 + lane;          // granule of 8 k
        float4 ha[4], hb[4];
        #pragma unroll
        for (int b = 0; b < 4; b++) {
            ha[b] = h4[b * (LSTM_H / 4) + g * 2];
            hb[b] = h4[b * (LSTM_H / 4) + g * 2 + 1];
        }
        #pragma unroll
        for (int r = 0; r < 4; r++) {
            const uint4* Wr = (const uint4*)(d_Whh + (size_t)(gw + r * LSTM_H) * LSTM_H);
            union { uint4 u; __half2 h[4]; } wu;
            wu.u = Wr[g];
            float2 f0 = __half22float2(wu.h[0]);
            float2 f1 = __half22float2(wu.h[1]);
            float2 f2 = __half22float2(wu.h[2]);
            float2 f3 = __half22float2(wu.h[3]);
            #pragma unroll
            for (int b = 0; b < 4; b++) {
                acc[r][b] += f0.x * ha[b].x + f0.y * ha[b].y
                           + f1.x * ha[b].z + f1.y * ha[b].w
                           + f2.x * hb[b].x + f2.y * hb[b].y
                           + f3.x * hb[b].z + f3.y * hb[b].w;
            }
        }
    }
    #pragma unroll
    for (int r = 0; r < 4; r++)
        #pragma unroll
        for (int b = 0; b < 4; b++)
            #pragma unroll
            for (int o = 16; o; o >>= 1)
                acc[r][b] += __shfl_xor_sync(0xffffffffu, acc[r][b], o);

    if (lane == 0) {
        #pragma unroll
        for (int b = 0; b < 4; b++) {
            size_t xb = ((size_t)b * TT + t) * G4;
            float gi = acc[0][b] + d_XP[xb + gw];
            float gf = acc[1][b] + d_XP[xb + gw + 4096];
            float gg = acc[2][b] + d_XP[xb + gw + 8192];
            float go = acc[3][b] + d_XP[xb + gw + 12288];
            float si = 1.f / (1.f + expf(-gi));
            float sf = 1.f / (1.f + expf(-gf));
            float so = 1.f / (1.f + expf(-go));
            float c = sf * d_C[b * LSTM_H + gw] + si * tanhf(gg);
            d_C[b * LSTM_H + gw] = c;
            hout[b * LSTM_H + gw] = so * tanhf(c);
        }
    }
}

// ---------------------------------------------------------------------------
// Final FC
// ---------------------------------------------------------------------------
__global__ void k_fc(const float* __restrict__ fcW, const float* __restrict__ fcb,
                     float* __restrict__ out) {
    int i = threadIdx.x;  // 0..127
    int b = i >> 5, n = i & 31;
    const float* h = &d_H[0][0] + b * LSTM_H + n * 128;  // T=32 -> parity 0
    float s = 0.f;
    #pragma unroll
    for (int l = 0; l < 128; l++) s += h[l] * fcW[l];
    out[i] = s + fcb[0];
}

extern "C" void kernel_launch(void* const* d_in, const int* in_sizes, int n_in,
                              void* d_out, int out_size) {
    const float* x       = (const float*)d_in[0];
    const void*  ei      = d_in[1];
    const float* ln_g    = (const float*)d_in[2];
    const float* ln_b    = (const float*)d_in[3];
    const float* W1      = (const float*)d_in[4];
    const float* b1      = (const float*)d_in[5];
    const float* W2      = (const float*)d_in[6];
    const float* b2      = (const float*)d_in[7];
    const float* Wih     = (const float*)d_in[8];
    const float* bih     = (const float*)d_in[9];
    const float* Whh     = (const float*)d_in[10];
    const float* bhh     = (const float*)d_in[11];
    const float* fcW     = (const float*)d_in[12];
    const float* fcb     = (const float*)d_in[13];

    __half* whh_h = nullptr;  cudaGetSymbolAddress((void**)&whh_h, d_Whh);
    __half* wih_h = nullptr;  cudaGetSymbolAddress((void**)&wih_h, d_Wih);

    k_setup<<<1, 256>>>((const long long*)ei, (const int*)ei);
    k_cvt<<<(G4 * LSTM_H / 8 + 255) / 256, 256>>>(Whh, whh_h, G4 * LSTM_H / 8);
    k_cvt<<<(G4 * LSTM_IN / 8 + 255) / 256, 256>>>(Wih, wih_h, G4 * LSTM_IN / 8);
    k_gcn<<<BB * TT, 256>>>(x, ln_g, ln_b, W1, b1, W2, b2);
    dim3 gx(G4 / 16, 8);
    k_xproj<<<gx, 256>>>(bih, bhh);
    for (int t = 0; t < TT; t++) k_step<<<512, 256>>>(t);
    k_fc<<<1, 128>>>(fcW, fcb, (float*)d_out);
}